// round 1
// baseline (speedup 1.0000x reference)
#include <cuda_runtime.h>
#include <cstdint>

#define N_NODES 100000
#define N_EDGES 1600000
#define D 128
#define D_OUT 16

#define SCAN_B 1024
#define NCHUNK ((N_NODES + SCAN_B - 1) / SCAN_B)   // 98

// ---------------- device scratch (static: no allocation allowed) ----------------
__device__ int   g_deg[N_NODES];
__device__ int   g_csr_ptr[N_NODES + 1];
__device__ int   g_cursor[N_NODES];
__device__ int   g_csr_src[N_EDGES];
__device__ int   g_bsum[NCHUNK];
__device__ float g_deg_inv[N_NODES];
__device__ float g_mean[(size_t)N_NODES * D];
__device__ float g_bufA[(size_t)N_NODES * D];
__device__ float g_bufB[(size_t)N_NODES * D];

// ---------------- CSR construction ----------------
__global__ void k_zero_deg() {
    int i = blockIdx.x * blockDim.x + threadIdx.x;
    if (i < N_NODES) g_deg[i] = 0;
}

__global__ void k_hist(const int* __restrict__ dst) {
    int e = blockIdx.x * blockDim.x + threadIdx.x;
    if (e < N_EDGES) atomicAdd(&g_deg[dst[e]], 1);
}

// per-chunk inclusive scan (Hillis-Steele), writes exclusive partials + block sums + deg_inv
__global__ void k_scan1() {
    __shared__ int s[SCAN_B];
    int gi = blockIdx.x * SCAN_B + threadIdx.x;
    int v = (gi < N_NODES) ? g_deg[gi] : 0;
    s[threadIdx.x] = v;
    __syncthreads();
#pragma unroll
    for (int off = 1; off < SCAN_B; off <<= 1) {
        int t = (threadIdx.x >= off) ? s[threadIdx.x - off] : 0;
        __syncthreads();
        s[threadIdx.x] += t;
        __syncthreads();
    }
    int inclusive = s[threadIdx.x];
    if (gi < N_NODES) {
        g_csr_ptr[gi] = inclusive - v;          // chunk-local exclusive
        g_deg_inv[gi] = 1.0f / (float)max(v, 1);
    }
    if (threadIdx.x == SCAN_B - 1) g_bsum[blockIdx.x] = inclusive;
}

__global__ void k_scan2() {
    __shared__ int s[NCHUNK];
    if (threadIdx.x < NCHUNK) s[threadIdx.x] = g_bsum[threadIdx.x];
    __syncthreads();
    if (threadIdx.x == 0) {
        int run = 0;
        for (int i = 0; i < NCHUNK; i++) { int t = s[i]; s[i] = run; run += t; }
    }
    __syncthreads();
    if (threadIdx.x < NCHUNK) g_bsum[threadIdx.x] = s[threadIdx.x];
}

__global__ void k_scan3() {
    int gi = blockIdx.x * blockDim.x + threadIdx.x;
    if (gi < N_NODES) {
        int p = g_csr_ptr[gi] + g_bsum[gi / SCAN_B];
        g_csr_ptr[gi] = p;
        g_cursor[gi]  = p;
    }
    if (gi == 0) g_csr_ptr[N_NODES] = N_EDGES;
}

__global__ void k_fill(const int* __restrict__ src, const int* __restrict__ dst) {
    int e = blockIdx.x * blockDim.x + threadIdx.x;
    if (e < N_EDGES) {
        int pos = atomicAdd(&g_cursor[dst[e]], 1);
        g_csr_src[pos] = src[e];
    }
}

// ---------------- mean aggregation: one warp per destination node ----------------
__global__ void k_aggregate(const float* __restrict__ in, float* __restrict__ out) {
    int warp = (blockIdx.x * blockDim.x + threadIdx.x) >> 5;
    int lane = threadIdx.x & 31;
    if (warp >= N_NODES) return;
    int beg = g_csr_ptr[warp];
    int end = g_csr_ptr[warp + 1];
    float4 acc = make_float4(0.f, 0.f, 0.f, 0.f);
    for (int e = beg; e < end; ++e) {
        int s = g_csr_src[e];
        float4 v = __ldg(((const float4*)(in + (size_t)s * D)) + lane);
        acc.x += v.x; acc.y += v.y; acc.z += v.z; acc.w += v.w;
    }
    float di = g_deg_inv[warp];
    acc.x *= di; acc.y *= di; acc.z *= di; acc.w *= di;
    ((float4*)(out + (size_t)warp * D))[lane] = acc;
}

// ---------------- fused SAGE GEMM: out = mean@Wn + x@Ws + b (opt. relu) ----------------
// 128x128 block tile, K=256 (phase 0: mean/Wn, phase 1: x/Ws), 256 threads, 8x8 microtile
#define BM 128
#define BK 16
__global__ void __launch_bounds__(256, 2)
k_sage_gemm(const float* __restrict__ Xs, const float* __restrict__ Mn,
            const float* __restrict__ Wn, const float* __restrict__ Ws,
            const float* __restrict__ bias, float* __restrict__ out, int relu) {
    __shared__ float As[BK][BM + 4];
    __shared__ float Bs[BK][D];
    const int block_row = blockIdx.x * BM;
    const int tid = threadIdx.x;
    const int tx = tid & 15;   // col group: 8 cols each
    const int ty = tid >> 4;   // row group: 8 rows each

    float acc[8][8];
#pragma unroll
    for (int i = 0; i < 8; i++)
#pragma unroll
        for (int j = 0; j < 8; j++) acc[i][j] = 0.f;

#pragma unroll 1
    for (int kt = 0; kt < 16; ++kt) {
        const int phase = kt >> 3;
        const int k0 = (kt & 7) * BK;
        const float* __restrict__ A = phase ? Xs : Mn;
        const float* __restrict__ W = phase ? Ws : Wn;

        // A tile -> As[k][m] (transposed). 512 float4 loads / 256 threads
#pragma unroll
        for (int r = 0; r < 2; ++r) {
            int idx = tid + r * 256;
            int m = idx >> 2;
            int c4 = idx & 3;
            int row = block_row + m;
            float4 v = make_float4(0.f, 0.f, 0.f, 0.f);
            if (row < N_NODES) v = *(const float4*)(A + (size_t)row * D + k0 + c4 * 4);
            As[c4 * 4 + 0][m] = v.x;
            As[c4 * 4 + 1][m] = v.y;
            As[c4 * 4 + 2][m] = v.z;
            As[c4 * 4 + 3][m] = v.w;
        }
        // B tile -> Bs[k][j]
#pragma unroll
        for (int r = 0; r < 2; ++r) {
            int idx = tid + r * 256;
            int k = idx >> 5;
            int c4 = idx & 31;
            float4 w = *(const float4*)(W + (size_t)(k0 + k) * D + c4 * 4);
            *(float4*)&Bs[k][c4 * 4] = w;
        }
        __syncthreads();

#pragma unroll
        for (int k = 0; k < BK; ++k) {
            float a[8], b[8];
#pragma unroll
            for (int i = 0; i < 8; i++) a[i] = As[k][ty * 8 + i];
#pragma unroll
            for (int j = 0; j < 8; j++) b[j] = Bs[k][tx * 8 + j];
#pragma unroll
            for (int i = 0; i < 8; i++)
#pragma unroll
                for (int j = 0; j < 8; j++) acc[i][j] += a[i] * b[j];
        }
        __syncthreads();
    }

    // epilogue: + bias, optional relu, store
#pragma unroll
    for (int i = 0; i < 8; i++) {
        int row = block_row + ty * 8 + i;
        if (row >= N_NODES) continue;
#pragma unroll
        for (int j4 = 0; j4 < 2; j4++) {
            int j0 = tx * 8 + j4 * 4;
            float4 o;
            o.x = acc[i][j4 * 4 + 0] + bias[j0 + 0];
            o.y = acc[i][j4 * 4 + 1] + bias[j0 + 1];
            o.z = acc[i][j4 * 4 + 2] + bias[j0 + 2];
            o.w = acc[i][j4 * 4 + 3] + bias[j0 + 3];
            if (relu) {
                o.x = fmaxf(o.x, 0.f); o.y = fmaxf(o.y, 0.f);
                o.z = fmaxf(o.z, 0.f); o.w = fmaxf(o.w, 0.f);
            }
            *(float4*)(out + (size_t)row * D + j0) = o;
        }
    }
}

// ---------------- final fc (128->16) + log_softmax, one warp per node ----------------
__global__ void k_fc_logsoftmax(const float* __restrict__ emb,
                                const float* __restrict__ Wfc,
                                const float* __restrict__ bfc,
                                float* __restrict__ outp) {
    __shared__ float sWt[D_OUT * D];   // transposed: sWt[j*128 + k]
    __shared__ float sb[D_OUT];
    for (int i = threadIdx.x; i < D * D_OUT; i += blockDim.x) {
        int k = i >> 4, j = i & 15;
        sWt[j * D + k] = Wfc[i];
    }
    if (threadIdx.x < D_OUT) sb[threadIdx.x] = bfc[threadIdx.x];
    __syncthreads();

    int warp = (blockIdx.x * blockDim.x + threadIdx.x) >> 5;
    int lane = threadIdx.x & 31;
    if (warp >= N_NODES) return;

    float4 e4 = ((const float4*)(emb + (size_t)warp * D))[lane];
    float y[D_OUT];
#pragma unroll
    for (int j = 0; j < D_OUT; j++) {
        float4 w = ((const float4*)(sWt + j * D))[lane];
        y[j] = e4.x * w.x + e4.y * w.y + e4.z * w.z + e4.w * w.w;
    }
    // butterfly reduce across warp -> every lane holds full y[j]
#pragma unroll
    for (int off = 16; off >= 1; off >>= 1)
#pragma unroll
        for (int j = 0; j < D_OUT; j++)
            y[j] += __shfl_xor_sync(0xFFFFFFFFu, y[j], off);

    float m = -1e30f;
#pragma unroll
    for (int j = 0; j < D_OUT; j++) { y[j] += sb[j]; m = fmaxf(m, y[j]); }
    float ssum = 0.f;
#pragma unroll
    for (int j = 0; j < D_OUT; j++) ssum += __expf(y[j] - m);
    float lse = __logf(ssum) + m;
    if (lane < D_OUT) outp[(size_t)warp * D_OUT + lane] = y[lane] - lse;
}

// ---------------- launcher ----------------
extern "C" void kernel_launch(void* const* d_in, const int* in_sizes, int n_in,
                              void* d_out, int out_size) {
    const float* x   = (const float*)d_in[0];
    const int*   ei  = (const int*)d_in[1];
    const float* Wn0 = (const float*)d_in[2];
    const float* Ws0 = (const float*)d_in[3];
    const float* b0  = (const float*)d_in[4];
    const float* Wn1 = (const float*)d_in[5];
    const float* Ws1 = (const float*)d_in[6];
    const float* b1  = (const float*)d_in[7];
    const float* Wn2 = (const float*)d_in[8];
    const float* Ws2 = (const float*)d_in[9];
    const float* b2  = (const float*)d_in[10];
    const float* Wfc = (const float*)d_in[11];
    const float* bfc = (const float*)d_in[12];

    float* out  = (float*)d_out;
    float* emb  = out;                               // [N, 128]
    float* logp = out + (size_t)N_NODES * D;         // [N, 16]

    const int* src = ei;
    const int* dst = ei + N_EDGES;

    void *p_mean, *p_A, *p_B;
    cudaGetSymbolAddress(&p_mean, g_mean);
    cudaGetSymbolAddress(&p_A, g_bufA);
    cudaGetSymbolAddress(&p_B, g_bufB);
    float* mean = (float*)p_mean;
    float* A = (float*)p_A;
    float* B = (float*)p_B;

    const int EB = (N_EDGES + 255) / 256;
    const int NB = (N_NODES + 255) / 256;
    const int GEMM_B = (N_NODES + BM - 1) / BM;   // 782
    const int WARP_B = (N_NODES * 32 + 255) / 256; // 12500

    // CSR build
    k_zero_deg<<<NB, 256>>>();
    k_hist<<<EB, 256>>>(dst);
    k_scan1<<<NCHUNK, SCAN_B>>>();
    k_scan2<<<1, 128>>>();
    k_scan3<<<NB, 256>>>();
    k_fill<<<EB, 256>>>(src, dst);

    // layer 0
    k_aggregate<<<WARP_B, 256>>>(x, mean);
    k_sage_gemm<<<GEMM_B, 256>>>(x, mean, Wn0, Ws0, b0, A, 1);
    // layer 1
    k_aggregate<<<WARP_B, 256>>>(A, mean);
    k_sage_gemm<<<GEMM_B, 256>>>(A, mean, Wn1, Ws1, b1, B, 1);
    // layer 2 -> emb directly into d_out
    k_aggregate<<<WARP_B, 256>>>(B, mean);
    k_sage_gemm<<<GEMM_B, 256>>>(B, mean, Wn2, Ws2, b2, emb, 0);
    // fc + log_softmax
    k_fc_logsoftmax<<<WARP_B, 256>>>(emb, Wfc, bfc, logp);
}